// round 11
// baseline (speedup 1.0000x reference)
#include <cuda_runtime.h>
#include <cstdint>

// Elman RNN split:
//   A) u[n,t,:] = x[n,t,:] @ W_ih^T + b_ih + b_hh   (parallel, streaming)
//   B) h_{t+1}  = tanh(u_t + h_t @ W_hh^T)          (serial, unit-per-thread)
// N=2048, T=512, I=32, H=64, O=1.
// B: 512 blocks x 64 threads x 4 samples. Thread j owns unit j for all 4
//    samples (W_hh row j = 64 regs). 8 independent 16-deep f32x2 chains.
//    Fixed per-step serial wall amortized over 4 samples per block.

#define TT 512
#define NN 2048

typedef unsigned long long ull;

__device__ float g_u[(size_t)NN * TT * 64];   // 268 MB scratch

__device__ __forceinline__ float tanh_acc(float s) {
    float e = __expf(2.0f * s);
    return 1.0f - __fdividef(2.0f, e + 1.0f);
}

// ---------------- Kernel A: streaming precompute of u, 4-row groups ----------------
__global__ void __launch_bounds__(128) precompute_u_kernel(
    const float* __restrict__ x,      // [N, T, I]
    const float* __restrict__ W_ih,   // [H, I]
    const float* __restrict__ b_ih,   // [H]
    const float* __restrict__ b_hh)   // [H]
{
    __shared__ __align__(16) float xs[4][2][128];   // [warp][parity][4 rows x 32]

    const int w  = threadIdx.x >> 5;
    const int l  = threadIdx.x & 31;
    const int n  = blockIdx.x;
    const int u0 = 2 * l;
    const int u1 = u0 + 1;

    ull W0[16], W1[16];
    {
        const ull* q0 = reinterpret_cast<const ull*>(W_ih + u0 * 32);
        const ull* q1 = reinterpret_cast<const ull*>(W_ih + u1 * 32);
        #pragma unroll
        for (int k = 0; k < 16; k++) { W0[k] = __ldg(q0 + k); W1[k] = __ldg(q1 + k); }
    }
    const float bias0 = __ldg(b_ih + u0) + __ldg(b_hh + u0);
    const float bias1 = __ldg(b_ih + u1) + __ldg(b_hh + u1);

    const int t0 = w * 128;
    const float* xb = x + (size_t)n * TT * 32;
    float* ub = g_u + (size_t)n * TT * 64;

    {
        const float4 v = __ldg(reinterpret_cast<const float4*>(xb + t0 * 32) + l);
        reinterpret_cast<float4*>(&xs[w][0][0])[l] = v;
    }
    __syncwarp();

    int p = 0;
    for (int g = 0; g < 32; g++) {
        float4 vn = make_float4(0.f, 0.f, 0.f, 0.f);
        if (g + 1 < 32)
            vn = __ldg(reinterpret_cast<const float4*>(xb + (t0 + 4 * (g + 1)) * 32) + l);

        #pragma unroll
        for (int r = 0; r < 4; r++) {
            const ulonglong2* vp =
                reinterpret_cast<const ulonglong2*>(&xs[w][p][r * 32]);
            ull a0 = 0ull, a1 = 0ull;
            #pragma unroll
            for (int q = 0; q < 8; q++) {
                const ulonglong2 v = vp[q];
                asm("fma.rn.f32x2 %0, %1, %2, %0;" : "+l"(a0) : "l"(v.x), "l"(W0[2 * q]));
                asm("fma.rn.f32x2 %0, %1, %2, %0;" : "+l"(a1) : "l"(v.x), "l"(W1[2 * q]));
                asm("fma.rn.f32x2 %0, %1, %2, %0;" : "+l"(a0) : "l"(v.y), "l"(W0[2 * q + 1]));
                asm("fma.rn.f32x2 %0, %1, %2, %0;" : "+l"(a1) : "l"(v.y), "l"(W1[2 * q + 1]));
            }
            float r0x, r0y, r1x, r1y;
            asm("mov.b64 {%0, %1}, %2;" : "=f"(r0x), "=f"(r0y) : "l"(a0));
            asm("mov.b64 {%0, %1}, %2;" : "=f"(r1x), "=f"(r1y) : "l"(a1));
            const int t = t0 + 4 * g + r;
            *reinterpret_cast<float2*>(ub + t * 64 + u0) =
                make_float2(bias0 + r0x + r0y, bias1 + r1x + r1y);
        }

        reinterpret_cast<float4*>(&xs[w][p ^ 1][0])[l] = vn;
        __syncwarp();
        p ^= 1;
    }
}

// ---------------- Kernel B: serial recurrence, unit-per-thread, 4 samples/block ----------------
__global__ void __launch_bounds__(64, 7) rnn_rec_kernel(
    const float* __restrict__ W_hh,   // [H, H]
    const float* __restrict__ fc_w,   // [1, H]
    const float* __restrict__ fc_b,   // [1]
    float* __restrict__ out)          // [N, 1]
{
    __shared__ __align__(16) float hb[2][4][64];   // [parity][sample][unit]
    __shared__ float wsum[2][4];                   // [warp][sample]

    const int j  = threadIdx.x;        // unit 0..63
    const int n0 = 4 * blockIdx.x;

    // W_hh row j: 32 ull = 64 regs
    ull W[32];
    {
        const ull* p = reinterpret_cast<const ull*>(W_hh + j * 64);
        #pragma unroll
        for (int k = 0; k < 32; k++) W[k] = __ldg(p + k);
    }

    // u streams for 4 samples
    const float* up0 = g_u + (size_t)(n0 + 0) * TT * 64 + j;
    const float* up1 = g_u + (size_t)(n0 + 1) * TT * 64 + j;
    const float* up2 = g_u + (size_t)(n0 + 2) * TT * 64 + j;
    const float* up3 = g_u + (size_t)(n0 + 3) * TT * 64 + j;

    hb[0][0][j] = 1.0f; hb[0][1][j] = 1.0f;
    hb[0][2][j] = 1.0f; hb[0][3][j] = 1.0f;

    float uc0 = __ldg(up0), uc1 = __ldg(up1), uc2 = __ldg(up2), uc3 = __ldg(up3);
    float un0 = __ldg(up0 + 64), un1 = __ldg(up1 + 64);
    float un2 = __ldg(up2 + 64), un3 = __ldg(up3 + 64);
    __syncthreads();

    float h0 = 1.0f, h1 = 1.0f, h2 = 1.0f, h3 = 1.0f;
    int par = 0;

    for (int t = 0; t < TT; t++) {
        // distance-2 prefetch of u_{t+2} (covers DRAM latency across ~2 step walls)
        float f0 = 0.f, f1 = 0.f, f2 = 0.f, f3 = 0.f;
        if (t + 2 < TT) {
            const int o = (t + 2) * 64;
            f0 = __ldg(up0 + o); f1 = __ldg(up1 + o);
            f2 = __ldg(up2 + o); f3 = __ldg(up3 + o);
        }

        const ulonglong2* vp0 = reinterpret_cast<const ulonglong2*>(&hb[par][0][0]);
        const ulonglong2* vp1 = reinterpret_cast<const ulonglong2*>(&hb[par][1][0]);
        const ulonglong2* vp2 = reinterpret_cast<const ulonglong2*>(&hb[par][2][0]);
        const ulonglong2* vp3 = reinterpret_cast<const ulonglong2*>(&hb[par][3][0]);

        // 8 chains: (sample 0..3) x (lo,hi); 16-deep each -> 64cy chain latency
        float2 s0 = make_float2(uc0, 0.0f);
        float2 s1 = make_float2(uc1, 0.0f);
        float2 s2 = make_float2(uc2, 0.0f);
        float2 s3 = make_float2(uc3, 0.0f);
        ull a0 = *reinterpret_cast<ull*>(&s0), b0 = 0ull;
        ull a1 = *reinterpret_cast<ull*>(&s1), b1 = 0ull;
        ull a2 = *reinterpret_cast<ull*>(&s2), b2 = 0ull;
        ull a3 = *reinterpret_cast<ull*>(&s3), b3 = 0ull;

        #pragma unroll
        for (int g = 0; g < 16; g++) {
            const ulonglong2 v0 = vp0[g];
            const ulonglong2 v1 = vp1[g];
            const ulonglong2 v2 = vp2[g];
            const ulonglong2 v3 = vp3[g];
            asm("fma.rn.f32x2 %0, %1, %2, %0;" : "+l"(a0) : "l"(v0.x), "l"(W[2 * g]));
            asm("fma.rn.f32x2 %0, %1, %2, %0;" : "+l"(a1) : "l"(v1.x), "l"(W[2 * g]));
            asm("fma.rn.f32x2 %0, %1, %2, %0;" : "+l"(a2) : "l"(v2.x), "l"(W[2 * g]));
            asm("fma.rn.f32x2 %0, %1, %2, %0;" : "+l"(a3) : "l"(v3.x), "l"(W[2 * g]));
            asm("fma.rn.f32x2 %0, %1, %2, %0;" : "+l"(b0) : "l"(v0.y), "l"(W[2 * g + 1]));
            asm("fma.rn.f32x2 %0, %1, %2, %0;" : "+l"(b1) : "l"(v1.y), "l"(W[2 * g + 1]));
            asm("fma.rn.f32x2 %0, %1, %2, %0;" : "+l"(b2) : "l"(v2.y), "l"(W[2 * g + 1]));
            asm("fma.rn.f32x2 %0, %1, %2, %0;" : "+l"(b3) : "l"(v3.y), "l"(W[2 * g + 1]));
        }

        asm("add.rn.f32x2 %0, %0, %1;" : "+l"(a0) : "l"(b0));
        asm("add.rn.f32x2 %0, %0, %1;" : "+l"(a1) : "l"(b1));
        asm("add.rn.f32x2 %0, %0, %1;" : "+l"(a2) : "l"(b2));
        asm("add.rn.f32x2 %0, %0, %1;" : "+l"(a3) : "l"(b3));

        float r0x, r0y, r1x, r1y, r2x, r2y, r3x, r3y;
        asm("mov.b64 {%0, %1}, %2;" : "=f"(r0x), "=f"(r0y) : "l"(a0));
        asm("mov.b64 {%0, %1}, %2;" : "=f"(r1x), "=f"(r1y) : "l"(a1));
        asm("mov.b64 {%0, %1}, %2;" : "=f"(r2x), "=f"(r2y) : "l"(a2));
        asm("mov.b64 {%0, %1}, %2;" : "=f"(r3x), "=f"(r3y) : "l"(a3));

        h0 = tanh_acc(r0x + r0y);
        h1 = tanh_acc(r1x + r1y);
        h2 = tanh_acc(r2x + r2y);
        h3 = tanh_acc(r3x + r3y);

        hb[par ^ 1][0][j] = h0;
        hb[par ^ 1][1][j] = h1;
        hb[par ^ 1][2][j] = h2;
        hb[par ^ 1][3][j] = h3;
        __syncthreads();

        uc0 = un0; un0 = f0;
        uc1 = un1; un1 = f1;
        uc2 = un2; un2 = f2;
        uc3 = un3; un3 = f3;
        par ^= 1;
    }

    // ---- output heads: sigmoid(h . fc_w + fc_b) for 4 samples ----
    const float fw = fc_w[j];
    float p0 = h0 * fw, p1 = h1 * fw, p2 = h2 * fw, p3 = h3 * fw;
    #pragma unroll
    for (int o = 16; o; o >>= 1) {
        p0 += __shfl_xor_sync(0xffffffffu, p0, o);
        p1 += __shfl_xor_sync(0xffffffffu, p1, o);
        p2 += __shfl_xor_sync(0xffffffffu, p2, o);
        p3 += __shfl_xor_sync(0xffffffffu, p3, o);
    }
    if ((j & 31) == 0) {
        const int w = j >> 5;
        wsum[w][0] = p0; wsum[w][1] = p1;
        wsum[w][2] = p2; wsum[w][3] = p3;
    }
    __syncthreads();
    if (j < 4) {
        const float s = wsum[0][j] + wsum[1][j] + fc_b[0];
        out[n0 + j] = __fdividef(1.0f, 1.0f + __expf(-s));
    }
}

extern "C" void kernel_launch(void* const* d_in, const int* in_sizes, int n_in,
                              void* d_out, int out_size) {
    const float* x    = (const float*)d_in[0];
    const float* W_ih = (const float*)d_in[1];
    const float* W_hh = (const float*)d_in[2];
    const float* b_ih = (const float*)d_in[3];
    const float* b_hh = (const float*)d_in[4];
    const float* fc_w = (const float*)d_in[5];
    const float* fc_b = (const float*)d_in[6];
    float* out = (float*)d_out;

    precompute_u_kernel<<<NN, 128>>>(x, W_ih, b_ih, b_hh);
    rnn_rec_kernel<<<NN / 4, 64>>>(W_hh, fc_w, fc_b, out);
}